// round 1
// baseline (speedup 1.0000x reference)
#include <cuda_runtime.h>
#include <cstdint>

#define T_DIM 1024
#define B_DIM 4
#define E_DIM 1024
#define H_DIM 16
#define HDIM  64
#define NBH   64          // B*H
#define MROWS 4096        // T*B
#define N3E   3072

// ------------------- scratch (device globals; no allocs allowed) ----------
__device__ float g_QRE[NBH * T_DIM * HDIM];
__device__ float g_QIM[NBH * T_DIM * HDIM];
__device__ float g_KP [NBH * T_DIM * HDIM];
__device__ float g_KM [NBH * T_DIM * HDIM];
__device__ float g_VRE[NBH * T_DIM * HDIM];
__device__ float g_VIM[NBH * T_DIM * HDIM];
__device__ float g_AWR[NBH * T_DIM * T_DIM];   // 256 MB raw scores
__device__ float g_ARE[MROWS * E_DIM];
__device__ float g_AIM[MROWS * E_DIM];
__device__ float g_VSUM[NBH * 128];
__device__ unsigned g_minU, g_maxU;

// ------------------- ordered-uint float encoding for atomic min/max ------
__device__ __forceinline__ unsigned encodeOrd(float f) {
    unsigned u = __float_as_uint(f);
    return (u & 0x80000000u) ? ~u : (u | 0x80000000u);
}
__device__ __forceinline__ float decodeOrd(unsigned u) {
    return (u & 0x80000000u) ? __uint_as_float(u & 0x7FFFFFFFu)
                             : __uint_as_float(~u);
}

__global__ void init_kernel() {
    g_minU = 0xFFFFFFFFu;
    g_maxU = 0u;
}

// ------------------- K1: complex in-projection ---------------------------
// C(m,n) = sum_k X(m,k) * W(n,k) complex ; M=4096, N=3072, K=1024
__global__ void __launch_bounds__(256) proj_kernel(
    const float* __restrict__ Xre, const float* __restrict__ Xim,
    const float* __restrict__ Wre, const float* __restrict__ Wim,
    const float* __restrict__ Bre, const float* __restrict__ Bim)
{
    __shared__ float Asr[16][64], Asi[16][64], Bsr[16][64], Bsi[16][64];
    const int tid = threadIdx.x;
    const int lr = tid >> 2;
    const int lk = (tid & 3) << 2;
    const int tx = tid & 15, ty = tid >> 4;
    const int m0 = blockIdx.y << 6;
    const int n0 = blockIdx.x << 6;

    float cre[4][4] = {}, cim[4][4] = {};

    const float* aRe = Xre + (size_t)(m0 + lr) * E_DIM + lk;
    const float* aIm = Xim + (size_t)(m0 + lr) * E_DIM + lk;
    const float* bRe = Wre + (size_t)(n0 + lr) * E_DIM + lk;
    const float* bIm = Wim + (size_t)(n0 + lr) * E_DIM + lk;

    for (int k0 = 0; k0 < E_DIM; k0 += 16) {
        float4 ar = *(const float4*)(aRe + k0);
        float4 ai = *(const float4*)(aIm + k0);
        float4 br = *(const float4*)(bRe + k0);
        float4 bi = *(const float4*)(bIm + k0);
        __syncthreads();
        Asr[lk+0][lr]=ar.x; Asr[lk+1][lr]=ar.y; Asr[lk+2][lr]=ar.z; Asr[lk+3][lr]=ar.w;
        Asi[lk+0][lr]=ai.x; Asi[lk+1][lr]=ai.y; Asi[lk+2][lr]=ai.z; Asi[lk+3][lr]=ai.w;
        Bsr[lk+0][lr]=br.x; Bsr[lk+1][lr]=br.y; Bsr[lk+2][lr]=br.z; Bsr[lk+3][lr]=br.w;
        Bsi[lk+0][lr]=bi.x; Bsi[lk+1][lr]=bi.y; Bsi[lk+2][lr]=bi.z; Bsi[lk+3][lr]=bi.w;
        __syncthreads();
        #pragma unroll
        for (int kk = 0; kk < 16; kk++) {
            float arh[4], aih[4], brh[4], bih[4];
            *(float4*)arh = *(const float4*)&Asr[kk][ty<<2];
            *(float4*)aih = *(const float4*)&Asi[kk][ty<<2];
            *(float4*)brh = *(const float4*)&Bsr[kk][tx<<2];
            *(float4*)bih = *(const float4*)&Bsi[kk][tx<<2];
            #pragma unroll
            for (int i = 0; i < 4; i++)
                #pragma unroll
                for (int j = 0; j < 4; j++) {
                    cre[i][j] += arh[i]*brh[j] - aih[i]*bih[j];
                    cim[i][j] += arh[i]*bih[j] + aih[i]*brh[j];
                }
        }
    }

    #pragma unroll
    for (int i = 0; i < 4; i++) {
        int m = m0 + (ty<<2) + i;
        int t = m >> 2, b = m & 3;
        #pragma unroll
        for (int j = 0; j < 4; j++) {
            int n = n0 + (tx<<2) + j;
            float re = cre[i][j] + Bre[n];
            float im = cim[i][j] + Bim[n];
            int sect = n >> 10;
            int e = n & 1023;
            int bh = b*16 + (e >> 6);
            int d = e & 63;
            int idx = (bh*T_DIM + t)*HDIM + d;
            if (sect == 0)      { g_QRE[idx] = re*0.125f; g_QIM[idx] = im*0.125f; }
            else if (sect == 1) { g_KP[idx]  = re + im;   g_KM[idx]  = re - im;  }
            else                { g_VRE[idx] = re;        g_VIM[idx] = im;       }
        }
    }
}

// ------------------- K1b: per-head V column sums -------------------------
__global__ void vsum_kernel() {
    int bh = blockIdx.x;
    int n = threadIdx.x;                       // 0..127
    const float* V = (n < 64 ? g_VRE : g_VIM) + bh*T_DIM*HDIM + (n & 63);
    float s = 0.f;
    for (int t = 0; t < T_DIM; t++) s += V[t*HDIM];
    g_VSUM[bh*128 + n] = s;
}

// ------------------- K2: batched QK^T (real form) + min/max --------------
// awr(t,t') = sum_d qre*kp + qim*km ; per head M=N=1024, K=64(x2)
__global__ void __launch_bounds__(256) qk_kernel()
{
    __shared__ float Qr[16][64], Qi[16][64], Kp[16][64], Km[16][64];
    __shared__ unsigned sMin[8], sMax[8];
    const int tid = threadIdx.x;
    const int lr = tid >> 2;
    const int lk = (tid & 3) << 2;
    const int tx = tid & 15, ty = tid >> 4;
    const int bh = blockIdx.z;
    const int m0 = blockIdx.y << 6, n0 = blockIdx.x << 6;

    const float* qre = g_QRE + bh*T_DIM*HDIM;
    const float* qim = g_QIM + bh*T_DIM*HDIM;
    const float* kp  = g_KP  + bh*T_DIM*HDIM;
    const float* km  = g_KM  + bh*T_DIM*HDIM;

    float acc[4][4] = {};

    for (int k0 = 0; k0 < HDIM; k0 += 16) {
        float4 a = *(const float4*)(qre + (m0+lr)*HDIM + k0 + lk);
        float4 b = *(const float4*)(qim + (m0+lr)*HDIM + k0 + lk);
        float4 c = *(const float4*)(kp  + (n0+lr)*HDIM + k0 + lk);
        float4 d = *(const float4*)(km  + (n0+lr)*HDIM + k0 + lk);
        __syncthreads();
        Qr[lk+0][lr]=a.x; Qr[lk+1][lr]=a.y; Qr[lk+2][lr]=a.z; Qr[lk+3][lr]=a.w;
        Qi[lk+0][lr]=b.x; Qi[lk+1][lr]=b.y; Qi[lk+2][lr]=b.z; Qi[lk+3][lr]=b.w;
        Kp[lk+0][lr]=c.x; Kp[lk+1][lr]=c.y; Kp[lk+2][lr]=c.z; Kp[lk+3][lr]=c.w;
        Km[lk+0][lr]=d.x; Km[lk+1][lr]=d.y; Km[lk+2][lr]=d.z; Km[lk+3][lr]=d.w;
        __syncthreads();
        #pragma unroll
        for (int kk = 0; kk < 16; kk++) {
            float qr4[4], qi4[4], kp4[4], km4[4];
            *(float4*)qr4 = *(const float4*)&Qr[kk][ty<<2];
            *(float4*)qi4 = *(const float4*)&Qi[kk][ty<<2];
            *(float4*)kp4 = *(const float4*)&Kp[kk][tx<<2];
            *(float4*)km4 = *(const float4*)&Km[kk][tx<<2];
            #pragma unroll
            for (int i = 0; i < 4; i++)
                #pragma unroll
                for (int j = 0; j < 4; j++)
                    acc[i][j] += qr4[i]*kp4[j] + qi4[i]*km4[j];
        }
    }

    unsigned umin = 0xFFFFFFFFu, umax = 0u;
    float* out = g_AWR + (size_t)bh * T_DIM * T_DIM;
    #pragma unroll
    for (int i = 0; i < 4; i++) {
        int m = m0 + (ty<<2) + i;
        #pragma unroll
        for (int j = 0; j < 4; j++) {
            int n = n0 + (tx<<2) + j;
            float v = acc[i][j];
            out[(size_t)m * T_DIM + n] = v;
            unsigned e = encodeOrd(v);
            umin = min(umin, e);
            umax = max(umax, e);
        }
    }
    #pragma unroll
    for (int o = 16; o > 0; o >>= 1) {
        umin = min(umin, __shfl_xor_sync(0xFFFFFFFFu, umin, o));
        umax = max(umax, __shfl_xor_sync(0xFFFFFFFFu, umax, o));
    }
    if ((tid & 31) == 0) { sMin[tid>>5] = umin; sMax[tid>>5] = umax; }
    __syncthreads();
    if (tid == 0) {
        umin = sMin[0]; umax = sMax[0];
        #pragma unroll
        for (int w = 1; w < 8; w++) { umin = min(umin, sMin[w]); umax = max(umax, sMax[w]); }
        atomicMin(&g_minU, umin);
        atomicMax(&g_maxU, umax);
    }
}

// ------------------- K3: AV with fused normalization ---------------------
// attn(t,d) = inv * ( sum_k awr_raw(t,k)*v(k,d) - gmin * vsum(d) )
__global__ void __launch_bounds__(256) attn_kernel()
{
    __shared__ float As[16][64], Bs[16][64];
    const int tid = threadIdx.x;
    const int lrA = tid >> 2;
    const int lkA = (tid & 3) << 2;
    const int lrB = tid >> 4;
    const int lcB = (tid & 15) << 2;
    const int tx = tid & 15, ty = tid >> 4;
    const int bh = blockIdx.z;
    const int m0 = blockIdx.x << 6;
    const int im_part = blockIdx.y;            // 0 -> v_re, 1 -> v_im

    const float* A = g_AWR + (size_t)bh * T_DIM * T_DIM;
    const float* V = (im_part ? g_VIM : g_VRE) + bh*T_DIM*HDIM;

    float acc[4][4] = {};

    for (int k0 = 0; k0 < T_DIM; k0 += 16) {
        float4 a = *(const float4*)(A + (size_t)(m0+lrA) * T_DIM + k0 + lkA);
        float4 b = *(const float4*)(V + (k0+lrB)*HDIM + lcB);
        __syncthreads();
        As[lkA+0][lrA]=a.x; As[lkA+1][lrA]=a.y; As[lkA+2][lrA]=a.z; As[lkA+3][lrA]=a.w;
        *(float4*)&Bs[lrB][lcB] = b;
        __syncthreads();
        #pragma unroll
        for (int kk = 0; kk < 16; kk++) {
            float a4[4], b4[4];
            *(float4*)a4 = *(const float4*)&As[kk][ty<<2];
            *(float4*)b4 = *(const float4*)&Bs[kk][tx<<2];
            #pragma unroll
            for (int i = 0; i < 4; i++)
                #pragma unroll
                for (int j = 0; j < 4; j++)
                    acc[i][j] += a4[i]*b4[j];
        }
    }

    float gmin = decodeOrd(g_minU);
    float gmax = decodeOrd(g_maxU);
    float inv = 1.0f / (gmax - gmin);
    int b = bh >> 4, h = bh & 15;
    float* OUT = im_part ? g_AIM : g_ARE;
    #pragma unroll
    for (int i = 0; i < 4; i++) {
        int t = m0 + (ty<<2) + i;
        #pragma unroll
        for (int j = 0; j < 4; j++) {
            int d = (tx<<2) + j;
            float vs = g_VSUM[bh*128 + im_part*64 + d];
            float val = (acc[i][j] - gmin*vs) * inv;
            OUT[(size_t)(t*B_DIM + b) * E_DIM + h*HDIM + d] = val;
        }
    }
}

// ------------------- K4: head-averaged attention map ----------------------
__global__ void avg_kernel(float* __restrict__ out)
{
    int idx = blockIdx.x * blockDim.x + threadIdx.x;   // 0..4M-1
    int b = idx >> 20;
    int off = idx & 0xFFFFF;
    const float* base = g_AWR + ((size_t)b << 24) + off;   // b * 16 heads * 1M
    float s = 0.f;
    #pragma unroll
    for (int h = 0; h < 16; h++) s += base[(size_t)h << 20];
    float gmin = decodeOrd(g_minU);
    float gmax = decodeOrd(g_maxU);
    out[idx] = (s * (1.0f/16.0f) - gmin) / (gmax - gmin);
}

// ------------------- K5: complex out-projection ---------------------------
__global__ void __launch_bounds__(256) outproj_kernel(
    const float* __restrict__ Wre, const float* __restrict__ Wim,
    const float* __restrict__ Bre, const float* __restrict__ Bim,
    float* __restrict__ outRe, float* __restrict__ outIm)
{
    __shared__ float Asr[16][64], Asi[16][64], Bsr[16][64], Bsi[16][64];
    const int tid = threadIdx.x;
    const int lr = tid >> 2;
    const int lk = (tid & 3) << 2;
    const int tx = tid & 15, ty = tid >> 4;
    const int m0 = blockIdx.y << 6;
    const int n0 = blockIdx.x << 6;

    float cre[4][4] = {}, cim[4][4] = {};

    const float* aRe = g_ARE + (size_t)(m0 + lr) * E_DIM + lk;
    const float* aIm = g_AIM + (size_t)(m0 + lr) * E_DIM + lk;
    const float* bRe = Wre + (size_t)(n0 + lr) * E_DIM + lk;
    const float* bIm = Wim + (size_t)(n0 + lr) * E_DIM + lk;

    for (int k0 = 0; k0 < E_DIM; k0 += 16) {
        float4 ar = *(const float4*)(aRe + k0);
        float4 ai = *(const float4*)(aIm + k0);
        float4 br = *(const float4*)(bRe + k0);
        float4 bi = *(const float4*)(bIm + k0);
        __syncthreads();
        Asr[lk+0][lr]=ar.x; Asr[lk+1][lr]=ar.y; Asr[lk+2][lr]=ar.z; Asr[lk+3][lr]=ar.w;
        Asi[lk+0][lr]=ai.x; Asi[lk+1][lr]=ai.y; Asi[lk+2][lr]=ai.z; Asi[lk+3][lr]=ai.w;
        Bsr[lk+0][lr]=br.x; Bsr[lk+1][lr]=br.y; Bsr[lk+2][lr]=br.z; Bsr[lk+3][lr]=br.w;
        Bsi[lk+0][lr]=bi.x; Bsi[lk+1][lr]=bi.y; Bsi[lk+2][lr]=bi.z; Bsi[lk+3][lr]=bi.w;
        __syncthreads();
        #pragma unroll
        for (int kk = 0; kk < 16; kk++) {
            float arh[4], aih[4], brh[4], bih[4];
            *(float4*)arh = *(const float4*)&Asr[kk][ty<<2];
            *(float4*)aih = *(const float4*)&Asi[kk][ty<<2];
            *(float4*)brh = *(const float4*)&Bsr[kk][tx<<2];
            *(float4*)bih = *(const float4*)&Bsi[kk][tx<<2];
            #pragma unroll
            for (int i = 0; i < 4; i++)
                #pragma unroll
                for (int j = 0; j < 4; j++) {
                    cre[i][j] += arh[i]*brh[j] - aih[i]*bih[j];
                    cim[i][j] += arh[i]*bih[j] + aih[i]*brh[j];
                }
        }
    }

    #pragma unroll
    for (int i = 0; i < 4; i++) {
        int m = m0 + (ty<<2) + i;
        #pragma unroll
        for (int j = 0; j < 4; j++) {
            int n = n0 + (tx<<2) + j;
            outRe[(size_t)m * E_DIM + n] = cre[i][j] + Bre[n];
            outIm[(size_t)m * E_DIM + n] = cim[i][j] + Bim[n];
        }
    }
}

// ------------------- launch ------------------------------------------------
extern "C" void kernel_launch(void* const* d_in, const int* in_sizes, int n_in,
                              void* d_out, int out_size)
{
    const float* x_re  = (const float*)d_in[0];
    const float* x_im  = (const float*)d_in[1];
    const float* w_re  = (const float*)d_in[2];
    const float* w_im  = (const float*)d_in[3];
    const float* b_re  = (const float*)d_in[4];
    const float* b_im  = (const float*)d_in[5];
    const float* ow_re = (const float*)d_in[6];
    const float* ow_im = (const float*)d_in[7];
    const float* ob_re = (const float*)d_in[8];
    const float* ob_im = (const float*)d_in[9];

    float* out_re = (float*)d_out;                       // (T,B,E)
    float* out_im = out_re + (size_t)MROWS * E_DIM;      // (T,B,E)
    float* aw_avg = out_im + (size_t)MROWS * E_DIM;      // (B,T,T)

    init_kernel<<<1, 1>>>();
    proj_kernel<<<dim3(N3E/64, MROWS/64), 256>>>(x_re, x_im, w_re, w_im, b_re, b_im);
    vsum_kernel<<<NBH, 128>>>();
    qk_kernel<<<dim3(T_DIM/64, T_DIM/64, NBH), 256>>>();
    attn_kernel<<<dim3(T_DIM/64, 2, NBH), 256>>>();
    avg_kernel<<<(B_DIM*T_DIM*T_DIM)/256, 256>>>(aw_avg);
    outproj_kernel<<<dim3(E_DIM/64, MROWS/64), 256>>>(ow_re, ow_im, ob_re, ob_im,
                                                      out_re, out_im);
}

// round 2
// speedup vs baseline: 2.2296x; 2.2296x over previous
#include <cuda_runtime.h>
#include <cstdint>

#define T_DIM 1024
#define B_DIM 4
#define E_DIM 1024
#define HDIM  64
#define NBH   64           // B*H
#define MROWS 4096         // T*B
#define KAUG  2048         // augmented K for proj/outproj
#define NAUG_P 6144        // augmented N for proj (2*3E)
#define NAUG_O 2048        // augmented N for outproj (2*E)

// ---------------- scratch ----------------
__device__ float g_XA [MROWS * KAUG];          // [Xre | Xim]           32MB
__device__ float g_WB [NAUG_P * KAUG];         // interleaved aug W      50MB
__device__ float g_OWB[NAUG_O * KAUG];         // interleaved aug OW     16MB
__device__ float g_AT2[MROWS * KAUG];          // attn out aug [re|im]   32MB
__device__ float g_Q  [NBH * T_DIM * 128];     // [qre*S | qim*S]        32MB
__device__ float g_K2 [NBH * T_DIM * 128];     // [kp | km]              32MB
__device__ float g_VT [NBH * 128 * T_DIM];     // transposed [vre;vim]   32MB
__device__ float g_AWR[(size_t)NBH * T_DIM * T_DIM]; // raw scores      256MB
__device__ float g_VSUM[NBH * 128];
__device__ unsigned g_minU, g_maxU;

// ---------------- helpers ----------------
__device__ __forceinline__ unsigned encodeOrd(float f) {
    unsigned u = __float_as_uint(f);
    return (u & 0x80000000u) ? ~u : (u | 0x80000000u);
}
__device__ __forceinline__ float decodeOrd(unsigned u) {
    return (u & 0x80000000u) ? __uint_as_float(u & 0x7FFFFFFFu)
                             : __uint_as_float(~u);
}
__device__ __forceinline__ float tf32r(float f) {
    uint32_t r;
    asm("cvt.rna.tf32.f32 %0, %1;" : "=r"(r) : "f"(f));
    return __uint_as_float(r);
}
__device__ __forceinline__ void mma8(float* c, const uint32_t* a, const uint32_t* b) {
    asm volatile(
        "mma.sync.aligned.m16n8k8.row.col.f32.tf32.tf32.f32 "
        "{%0,%1,%2,%3}, {%4,%5,%6,%7}, {%8,%9}, {%0,%1,%2,%3};"
        : "+f"(c[0]), "+f"(c[1]), "+f"(c[2]), "+f"(c[3])
        : "r"(a[0]), "r"(a[1]), "r"(a[2]), "r"(a[3]), "r"(b[0]), "r"(b[1]));
}

__global__ void init_kernel() { g_minU = 0xFFFFFFFFu; g_maxU = 0u; }

// ---------------- shared tf32 GEMM core: C(128x128) = A(128xK) * B(128xK)^T
// A row-major (lda), B row-major (ldb). 256 threads, 8 warps in 2x4.
#define KT 16
struct SmemGemm { float As[128][20]; float Bs[128][20]; };

__device__ __forceinline__ void gemm_core(
    const float* __restrict__ A, const float* __restrict__ B,
    int lda, int ldb, int K, float (&acc)[4][4][4], SmemGemm& sm)
{
    const int tid = threadIdx.x;
    const int lane = tid & 31;
    const int warp = tid >> 5;
    const int wm = (warp >> 2) * 64;
    const int wn = (warp & 3) * 32;
    const int g = lane >> 2, tg = lane & 3;
    const int lrow = tid >> 1, lk = (tid & 1) * 8;

    const float* Ap = A + (size_t)lrow * lda + lk;
    const float* Bp = B + (size_t)lrow * ldb + lk;

    float4 ra0 = *(const float4*)(Ap);
    float4 ra1 = *(const float4*)(Ap + 4);
    float4 rb0 = *(const float4*)(Bp);
    float4 rb1 = *(const float4*)(Bp + 4);

    // store first tile
    {
        float* as = &sm.As[lrow][lk];
        as[0]=tf32r(ra0.x); as[1]=tf32r(ra0.y); as[2]=tf32r(ra0.z); as[3]=tf32r(ra0.w);
        as[4]=tf32r(ra1.x); as[5]=tf32r(ra1.y); as[6]=tf32r(ra1.z); as[7]=tf32r(ra1.w);
        float* bs = &sm.Bs[lrow][lk];
        bs[0]=tf32r(rb0.x); bs[1]=tf32r(rb0.y); bs[2]=tf32r(rb0.z); bs[3]=tf32r(rb0.w);
        bs[4]=tf32r(rb1.x); bs[5]=tf32r(rb1.y); bs[6]=tf32r(rb1.z); bs[7]=tf32r(rb1.w);
    }
    __syncthreads();

    int k0 = KT;
    while (true) {
        bool has_next = (k0 < K);
        if (has_next) {
            ra0 = *(const float4*)(Ap + k0);
            ra1 = *(const float4*)(Ap + k0 + 4);
            rb0 = *(const float4*)(Bp + k0);
            rb1 = *(const float4*)(Bp + k0 + 4);
        }
        #pragma unroll
        for (int ks = 0; ks < KT; ks += 8) {
            uint32_t af[4][4], bf[4][2];
            #pragma unroll
            for (int i = 0; i < 4; i++) {
                int m = wm + i * 16 + g;
                af[i][0] = __float_as_uint(sm.As[m][ks + tg]);
                af[i][1] = __float_as_uint(sm.As[m + 8][ks + tg]);
                af[i][2] = __float_as_uint(sm.As[m][ks + 4 + tg]);
                af[i][3] = __float_as_uint(sm.As[m + 8][ks + 4 + tg]);
            }
            #pragma unroll
            for (int j = 0; j < 4; j++) {
                int n = wn + j * 8 + g;
                bf[j][0] = __float_as_uint(sm.Bs[n][ks + tg]);
                bf[j][1] = __float_as_uint(sm.Bs[n][ks + 4 + tg]);
            }
            #pragma unroll
            for (int i = 0; i < 4; i++)
                #pragma unroll
                for (int j = 0; j < 4; j++)
                    mma8(acc[i][j], af[i], bf[j]);
        }
        if (!has_next) break;
        __syncthreads();
        {
            float* as = &sm.As[lrow][lk];
            as[0]=tf32r(ra0.x); as[1]=tf32r(ra0.y); as[2]=tf32r(ra0.z); as[3]=tf32r(ra0.w);
            as[4]=tf32r(ra1.x); as[5]=tf32r(ra1.y); as[6]=tf32r(ra1.z); as[7]=tf32r(ra1.w);
            float* bs = &sm.Bs[lrow][lk];
            bs[0]=tf32r(rb0.x); bs[1]=tf32r(rb0.y); bs[2]=tf32r(rb0.z); bs[3]=tf32r(rb0.w);
            bs[4]=tf32r(rb1.x); bs[5]=tf32r(rb1.y); bs[6]=tf32r(rb1.z); bs[7]=tf32r(rb1.w);
        }
        __syncthreads();
        k0 += KT;
    }
}

// fragment element coordinates: rows r0, r0+8 ; cols c, c+1 (c even)
#define FRAG_COORDS \
    const int lane = threadIdx.x & 31; \
    const int warp = threadIdx.x >> 5; \
    const int wm = (warp >> 2) * 64, wn = (warp & 3) * 32; \
    const int g = lane >> 2, tg = lane & 3;

// ---------------- packing kernels ----------------
__global__ void pack_x(const float* __restrict__ xre, const float* __restrict__ xim) {
    int i = blockIdx.x * 256 + threadIdx.x;
    int m = i >> 11, k = i & 2047;
    g_XA[i] = (k < 1024) ? xre[m * 1024 + k] : xim[m * 1024 + k - 1024];
}
__global__ void pack_w(const float* __restrict__ wre, const float* __restrict__ wim) {
    int i = blockIdx.x * 256 + threadIdx.x;       // over 6144*2048
    int row = i >> 11, k = i & 2047;
    int n = row >> 1, p = row & 1;
    float v;
    if (p == 0) v = (k < 1024) ? wre[n * 1024 + k] : -wim[n * 1024 + k - 1024];
    else        v = (k < 1024) ? wim[n * 1024 + k] :  wre[n * 1024 + k - 1024];
    g_WB[i] = v;
}
__global__ void pack_ow(const float* __restrict__ wre, const float* __restrict__ wim) {
    int i = blockIdx.x * 256 + threadIdx.x;       // over 2048*2048
    int row = i >> 11, k = i & 2047;
    int n = row >> 1, p = row & 1;
    float v;
    if (p == 0) v = (k < 1024) ? wre[n * 1024 + k] : -wim[n * 1024 + k - 1024];
    else        v = (k < 1024) ? wim[n * 1024 + k] :  wre[n * 1024 + k - 1024];
    g_OWB[i] = v;
}

// ---------------- K1: in-projection (augmented complex GEMM) -------------
__global__ void __launch_bounds__(256) proj_kernel(
    const float* __restrict__ Bre, const float* __restrict__ Bim)
{
    __shared__ SmemGemm sm;
    float acc[4][4][4] = {};
    const int m0 = blockIdx.y << 7;
    const int n0 = blockIdx.x << 7;   // augmented col base
    gemm_core(g_XA + (size_t)m0 * KAUG, g_WB + (size_t)n0 * KAUG,
              KAUG, KAUG, KAUG, acc, sm);
    FRAG_COORDS;
    #pragma unroll
    for (int i = 0; i < 4; i++) {
        #pragma unroll
        for (int j = 0; j < 4; j++) {
            int na = n0 + wn + j * 8 + 2 * tg;    // even
            int n = na >> 1;
            int sect = n >> 10, e = n & 1023;
            int bh_base = (e >> 6), d = e & 63;
            float bre = Bre[n], bim = Bim[n];
            #pragma unroll
            for (int rr = 0; rr < 2; rr++) {
                int m = m0 + wm + i * 16 + g + rr * 8;
                float re = acc[i][j][rr * 2 + 0] + bre;
                float im = acc[i][j][rr * 2 + 1] + bim;
                int t = m >> 2, b = m & 3;
                int bh = b * 16 + bh_base;
                if (sect == 0) {
                    int idx = (bh * T_DIM + t) * 128 + d;
                    g_Q[idx] = re * 0.125f; g_Q[idx + 64] = im * 0.125f;
                } else if (sect == 1) {
                    int idx = (bh * T_DIM + t) * 128 + d;
                    g_K2[idx] = re + im; g_K2[idx + 64] = re - im;
                } else {
                    int idx = (bh * 128 + d) * T_DIM + t;
                    g_VT[idx] = re; g_VT[idx + 64 * T_DIM] = im;
                }
            }
        }
    }
}

// ---------------- K1b: per-head V column sums (rows of VT) ---------------
__global__ void vsum_kernel() {
    int rowid = blockIdx.x * 8 + (threadIdx.x >> 5);   // 0..8191
    int lane = threadIdx.x & 31;
    const float* p = g_VT + (size_t)rowid * T_DIM;
    float s = 0.f;
    for (int t = lane; t < T_DIM; t += 32) s += p[t];
    #pragma unroll
    for (int o = 16; o; o >>= 1) s += __shfl_xor_sync(0xFFFFFFFFu, s, o);
    if (!lane) g_VSUM[rowid] = s;
}

// ---------------- K2: batched QK^T + global min/max ----------------------
__global__ void __launch_bounds__(256) qk_kernel()
{
    __shared__ SmemGemm sm;
    __shared__ unsigned sMin[8], sMax[8];
    float acc[4][4][4] = {};
    const int bh = blockIdx.z;
    const int m0 = blockIdx.y << 7;
    const int n0 = blockIdx.x << 7;
    const float* A = g_Q  + (size_t)bh * T_DIM * 128 + (size_t)m0 * 128;
    const float* B = g_K2 + (size_t)bh * T_DIM * 128 + (size_t)n0 * 128;
    gemm_core(A, B, 128, 128, 128, acc, sm);
    FRAG_COORDS;
    float* out = g_AWR + (size_t)bh * T_DIM * T_DIM;
    unsigned umin = 0xFFFFFFFFu, umax = 0u;
    #pragma unroll
    for (int i = 0; i < 4; i++) {
        #pragma unroll
        for (int j = 0; j < 4; j++) {
            int n = n0 + wn + j * 8 + 2 * tg;
            #pragma unroll
            for (int rr = 0; rr < 2; rr++) {
                int m = m0 + wm + i * 16 + g + rr * 8;
                float v0 = acc[i][j][rr * 2 + 0];
                float v1 = acc[i][j][rr * 2 + 1];
                *(float2*)(out + (size_t)m * T_DIM + n) = make_float2(v0, v1);
                unsigned e0 = encodeOrd(v0), e1 = encodeOrd(v1);
                umin = min(umin, min(e0, e1));
                umax = max(umax, max(e0, e1));
            }
        }
    }
    #pragma unroll
    for (int o = 16; o; o >>= 1) {
        umin = min(umin, __shfl_xor_sync(0xFFFFFFFFu, umin, o));
        umax = max(umax, __shfl_xor_sync(0xFFFFFFFFu, umax, o));
    }
    if (!lane) { sMin[warp] = umin; sMax[warp] = umax; }
    __syncthreads();
    if (threadIdx.x == 0) {
        umin = sMin[0]; umax = sMax[0];
        #pragma unroll
        for (int w = 1; w < 8; w++) { umin = min(umin, sMin[w]); umax = max(umax, sMax[w]); }
        atomicMin(&g_minU, umin);
        atomicMax(&g_maxU, umax);
    }
}

// ---------------- K3: AV (raw scores) with fused normalization -----------
// C[t][dd] = sum_k awr[t][k] * VT[dd][k]; then (C - gmin*vsum)*inv, scatter
__global__ void __launch_bounds__(256) attn_kernel()
{
    __shared__ SmemGemm sm;
    float acc[4][4][4] = {};
    const int bh = blockIdx.z;
    const int m0 = blockIdx.y << 7;
    const float* A = g_AWR + (size_t)bh * T_DIM * T_DIM + (size_t)m0 * T_DIM;
    const float* B = g_VT  + (size_t)bh * 128 * T_DIM;
    gemm_core(A, B, T_DIM, T_DIM, T_DIM, acc, sm);
    FRAG_COORDS;
    float gmin = decodeOrd(g_minU);
    float gmax = decodeOrd(g_maxU);
    float inv = 1.0f / (gmax - gmin);
    int b = bh >> 4, h = bh & 15;
    #pragma unroll
    for (int i = 0; i < 4; i++) {
        #pragma unroll
        for (int j = 0; j < 4; j++) {
            int dd = wn + j * 8 + 2 * tg;     // even, 0..126
            float vs0 = g_VSUM[bh * 128 + dd];
            float vs1 = g_VSUM[bh * 128 + dd + 1];
            int col0 = (dd < 64)     ? h * 64 + dd           : 1024 + h * 64 + dd - 64;
            int col1 = (dd + 1 < 64) ? h * 64 + dd + 1       : 1024 + h * 64 + dd + 1 - 64;
            #pragma unroll
            for (int rr = 0; rr < 2; rr++) {
                int t = m0 + wm + i * 16 + g + rr * 8;
                int m2 = t * B_DIM + b;
                float v0 = (acc[i][j][rr * 2 + 0] - gmin * vs0) * inv;
                float v1 = (acc[i][j][rr * 2 + 1] - gmin * vs1) * inv;
                g_AT2[(size_t)m2 * KAUG + col0] = v0;
                g_AT2[(size_t)m2 * KAUG + col1] = v1;
            }
        }
    }
}

// ---------------- K4: head-averaged attention map ------------------------
__global__ void avg_kernel(float* __restrict__ out)
{
    int idx = blockIdx.x * blockDim.x + threadIdx.x;   // 0..4M-1
    int b = idx >> 20;
    int off = idx & 0xFFFFF;
    const float* base = g_AWR + ((size_t)b << 24) + off;
    float s = 0.f;
    #pragma unroll
    for (int h = 0; h < 16; h++) s += base[(size_t)h << 20];
    float gmin = decodeOrd(g_minU);
    float gmax = decodeOrd(g_maxU);
    out[idx] = (s * (1.0f / 16.0f) - gmin) / (gmax - gmin);
}

// ---------------- K5: out-projection (augmented complex GEMM) ------------
__global__ void __launch_bounds__(256) outproj_kernel(
    const float* __restrict__ Bre, const float* __restrict__ Bim,
    float* __restrict__ outRe, float* __restrict__ outIm)
{
    __shared__ SmemGemm sm;
    float acc[4][4][4] = {};
    const int m0 = blockIdx.y << 7;
    const int n0 = blockIdx.x << 7;   // augmented (0..2047)
    gemm_core(g_AT2 + (size_t)m0 * KAUG, g_OWB + (size_t)n0 * KAUG,
              KAUG, KAUG, KAUG, acc, sm);
    FRAG_COORDS;
    #pragma unroll
    for (int i = 0; i < 4; i++) {
        #pragma unroll
        for (int j = 0; j < 4; j++) {
            int na = n0 + wn + j * 8 + 2 * tg;
            int n = na >> 1;
            float bre = Bre[n], bim = Bim[n];
            #pragma unroll
            for (int rr = 0; rr < 2; rr++) {
                int m = m0 + wm + i * 16 + g + rr * 8;
                outRe[(size_t)m * E_DIM + n] = acc[i][j][rr * 2 + 0] + bre;
                outIm[(size_t)m * E_DIM + n] = acc[i][j][rr * 2 + 1] + bim;
            }
        }
    }
}

// ---------------- launch ----------------
extern "C" void kernel_launch(void* const* d_in, const int* in_sizes, int n_in,
                              void* d_out, int out_size)
{
    const float* x_re  = (const float*)d_in[0];
    const float* x_im  = (const float*)d_in[1];
    const float* w_re  = (const float*)d_in[2];
    const float* w_im  = (const float*)d_in[3];
    const float* b_re  = (const float*)d_in[4];
    const float* b_im  = (const float*)d_in[5];
    const float* ow_re = (const float*)d_in[6];
    const float* ow_im = (const float*)d_in[7];
    const float* ob_re = (const float*)d_in[8];
    const float* ob_im = (const float*)d_in[9];

    float* out_re = (float*)d_out;
    float* out_im = out_re + (size_t)MROWS * E_DIM;
    float* aw_avg = out_im + (size_t)MROWS * E_DIM;

    init_kernel<<<1, 1>>>();
    pack_x <<<(MROWS * KAUG) / 256, 256>>>(x_re, x_im);
    pack_w <<<(NAUG_P * KAUG) / 256, 256>>>(w_re, w_im);
    pack_ow<<<(NAUG_O * KAUG) / 256, 256>>>(ow_re, ow_im);

    proj_kernel<<<dim3(NAUG_P / 128, MROWS / 128), 256>>>(b_re, b_im);
    vsum_kernel<<<(NBH * 128) / 8, 256>>>();
    qk_kernel<<<dim3(T_DIM / 128, T_DIM / 128, NBH), 256>>>();
    attn_kernel<<<dim3(1, T_DIM / 128, NBH), 256>>>();
    avg_kernel<<<(B_DIM * T_DIM * T_DIM) / 256, 256>>>(aw_avg);
    outproj_kernel<<<dim3(NAUG_O / 128, MROWS / 128), 256>>>(ob_re, ob_im,
                                                             out_re, out_im);
}